// round 15
// baseline (speedup 1.0000x reference)
#include <cuda_runtime.h>
#include <cuda_fp16.h>
#include <math.h>
#include <string.h>
#include <stdint.h>

// ---------------- problem constants ----------------
constexpr int B  = 4;
constexpr int S  = 2048;
constexpr int E  = 1024;
constexpr int CS = 16;
constexpr int NC = 8;
constexpr int H  = 16;
constexpr int D  = E + CS;      // 1040
constexpr int DH = D / H;       // 65
constexpr int DHP = 80;         // padded head dim
constexpr int DFF = 4 * E;      // 4096
constexpr int MT = B * S;       // 8192

// ---------------- arena (bytes) ----------------
constexpr size_t AL(size_t x) { return (x + 255) & ~(size_t)255; }
constexpr size_t SZ_XCH = (size_t)MT * D * 2;
constexpr size_t SZ_XNF = (size_t)MT * E * 4;
constexpr size_t SZ_HP  = (size_t)B * H * S * DHP * 2;
constexpr size_t SZ_OB  = (size_t)MT * D * 2;
constexpr size_t SZ_HBH = (size_t)MT * E * 2;
constexpr size_t SZ_HBF = (size_t)MT * E * 4;
constexpr size_t SZ_FF  = (size_t)MT * DFF * 2;
constexpr size_t SZ_YB  = (size_t)MT * E * 4;
constexpr size_t SZ_AP  = (size_t)MT * NC * D * 2;
constexpr size_t SZ_WDD = (size_t)D * D * 2;
constexpr size_t SZ_WK  = (size_t)NC * D * D * 2;
constexpr size_t SZ_WF  = (size_t)DFF * E * 2;

constexpr size_t O_XCH = 0;
constexpr size_t O_XNF = AL(O_XCH + SZ_XCH);
constexpr size_t O_QP  = AL(O_XNF + SZ_XNF);
constexpr size_t O_KP  = AL(O_QP  + SZ_HP);
constexpr size_t O_VT  = AL(O_KP  + SZ_HP);
constexpr size_t O_OB  = AL(O_VT  + SZ_HP);
constexpr size_t O_HBH = AL(O_OB  + SZ_OB);
constexpr size_t O_HBF = AL(O_HBH + SZ_HBH);
constexpr size_t O_FF  = AL(O_HBF + SZ_HBF);
constexpr size_t O_YB  = AL(O_FF  + SZ_FF);
constexpr size_t O_AP  = AL(O_YB  + SZ_YB);
constexpr size_t O_WQ  = AL(O_AP  + SZ_AP);
constexpr size_t O_WV  = AL(O_WQ  + SZ_WDD);
constexpr size_t O_WO  = AL(O_WV  + SZ_WDD);
constexpr size_t O_WK  = AL(O_WO  + SZ_WDD);
constexpr size_t O_WF1 = AL(O_WK  + SZ_WK);
constexpr size_t O_WF2 = AL(O_WF1 + SZ_WF);
constexpr size_t ARENA_BYTES = O_WF2 + SZ_WF;

__device__ __align__(256) unsigned char g_arena[ARENA_BYTES];

// ---------------- helpers ----------------
__device__ __forceinline__ uint32_t smem_u32(const void* p) {
    uint32_t a;
    asm("{ .reg .u64 t; cvta.to.shared.u64 t, %1; cvt.u32.u64 %0, t; }" : "=r"(a) : "l"(p));
    return a;
}

__device__ __forceinline__ uint32_t h2u(__half2 h) {
    uint32_t u;
    memcpy(&u, &h, 4);
    return u;
}

__device__ __forceinline__ void mma_f16(float* c, const uint32_t* a, const uint32_t* b) {
    asm volatile(
        "mma.sync.aligned.m16n8k16.row.col.f32.f16.f16.f32 "
        "{%0,%1,%2,%3}, {%4,%5,%6,%7}, {%8,%9}, {%0,%1,%2,%3};"
        : "+f"(c[0]), "+f"(c[1]), "+f"(c[2]), "+f"(c[3])
        : "r"(a[0]), "r"(a[1]), "r"(a[2]), "r"(a[3]), "r"(b[0]), "r"(b[1]));
}

__device__ __forceinline__ void ldm_x4(uint32_t* r, uint32_t addr) {
    asm volatile("ldmatrix.sync.aligned.m8n8.x4.shared.b16 {%0,%1,%2,%3}, [%4];"
                 : "=r"(r[0]), "=r"(r[1]), "=r"(r[2]), "=r"(r[3]) : "r"(addr));
}

__device__ __forceinline__ void cp16(uint32_t dst, const void* src, int sz) {
    asm volatile("cp.async.cg.shared.global [%0], [%1], 16, %2;"
                 :: "r"(dst), "l"(src), "r"(sz));
}

__device__ __forceinline__ float blk_sum256(float v, float* red8) {
    #pragma unroll
    for (int o = 16; o > 0; o >>= 1) v += __shfl_xor_sync(0xffffffffu, v, o);
    __syncthreads();
    if ((threadIdx.x & 31) == 0) red8[threadIdx.x >> 5] = v;
    __syncthreads();
    if (threadIdx.x == 0) {
        float t = 0.f;
        #pragma unroll
        for (int i = 0; i < 8; i++) t += red8[i];
        red8[0] = t;
    }
    __syncthreads();
    return red8[0];
}

// ---------------- fp32 -> fp16 weight convert ----------------
__global__ void w2h_kernel(const float* __restrict__ src, __half* __restrict__ dst, int n8) {
    int i = blockIdx.x * blockDim.x + threadIdx.x;
    if (i < n8) {
        float4 a = ((const float4*)src)[2 * i];
        float4 b = ((const float4*)src)[2 * i + 1];
        __half h[8];
        h[0] = __float2half_rn(a.x); h[1] = __float2half_rn(a.y);
        h[2] = __float2half_rn(a.z); h[3] = __float2half_rn(a.w);
        h[4] = __float2half_rn(b.x); h[5] = __float2half_rn(b.y);
        h[6] = __float2half_rn(b.z); h[7] = __float2half_rn(b.w);
        ((uint4*)dst)[i] = *(const uint4*)h;
    }
}

// ---------------- ones row for V^T (sum column trick) ----------------
__global__ void ones_row_kernel(__half* __restrict__ vt) {
    const size_t base = ((size_t)blockIdx.x * DHP + DH) * S;
    uint4 v;
    v.x = v.y = v.z = v.w = 0x3C003C00u;   // 1.0h x8
    ((uint4*)(vt + base))[threadIdx.x] = v;
}

// ---------------- LayerNorm + concat ----------------
__global__ void ln_concat_kernel(const float* __restrict__ x,
                                 const float* __restrict__ cond,
                                 const float* __restrict__ g,
                                 const float* __restrict__ bta,
                                 __half* __restrict__ xch,
                                 float* __restrict__ xnf) {
    __shared__ float red8[8];
    const int s   = blockIdx.x;
    const int tid = threadIdx.x;
    const float* xr = x + (size_t)s * E;
    float v0 = xr[tid], v1 = xr[tid + 256], v2 = xr[tid + 512], v3 = xr[tid + 768];
    float mean = blk_sum256(v0 + v1 + v2 + v3, red8) * (1.0f / E);
    float d0 = v0 - mean, d1 = v1 - mean, d2 = v2 - mean, d3 = v3 - mean;
    float var = blk_sum256(d0 * d0 + d1 * d1 + d2 * d2 + d3 * d3, red8) * (1.0f / E);
    float rstd = rsqrtf(var + 1e-5f);
    __half* xo = xch + (size_t)s * D;
    float*  xf = xnf + (size_t)s * E;
    float r0 = d0 * rstd * g[tid      ] + bta[tid      ];
    float r1 = d1 * rstd * g[tid + 256] + bta[tid + 256];
    float r2 = d2 * rstd * g[tid + 512] + bta[tid + 512];
    float r3 = d3 * rstd * g[tid + 768] + bta[tid + 768];
    xo[tid] = __float2half_rn(r0);  xf[tid] = r0;
    xo[tid + 256] = __float2half_rn(r1);  xf[tid + 256] = r1;
    xo[tid + 512] = __float2half_rn(r2);  xf[tid + 512] = r2;
    xo[tid + 768] = __float2half_rn(r3);  xf[tid + 768] = r3;
    if (tid < CS) xo[E + tid] = __float2half_rn(cond[(size_t)s * CS + tid]);
}

// ---------------- final LayerNorm ----------------
__global__ void ln_final_kernel(const float* __restrict__ y,
                                const float* __restrict__ g,
                                const float* __restrict__ bta,
                                float* __restrict__ out) {
    __shared__ float red8[8];
    const int s   = blockIdx.x;
    const int tid = threadIdx.x;
    const float* yr = y + (size_t)s * E;
    float v0 = yr[tid], v1 = yr[tid + 256], v2 = yr[tid + 512], v3 = yr[tid + 768];
    float mean = blk_sum256(v0 + v1 + v2 + v3, red8) * (1.0f / E);
    float d0 = v0 - mean, d1 = v1 - mean, d2 = v2 - mean, d3 = v3 - mean;
    float var = blk_sum256(d0 * d0 + d1 * d1 + d2 * d2 + d3 * d3, red8) * (1.0f / E);
    float rstd = rsqrtf(var + 1e-5f);
    float* o = out + (size_t)s * E;
    o[tid      ] = d0 * rstd * g[tid      ] + bta[tid      ];
    o[tid + 256] = d1 * rstd * g[tid + 256] + bta[tid + 256];
    o[tid + 512] = d2 * rstd * g[tid + 512] + bta[tid + 512];
    o[tid + 768] = d3 * rstd * g[tid + 768] + bta[tid + 768];
}

// ---------------- build A' = w[m,c] * xc[m,d] (half) ----------------
__global__ void build_ap_kernel(const __half* __restrict__ xch,
                                const float* __restrict__ cond,
                                __half* __restrict__ ap) {
    __shared__ float xrow[D];
    __shared__ float w8[NC];
    const int m   = blockIdx.x;
    const int tid = threadIdx.x;
    if (tid < NC) w8[tid] = cond[(size_t)m * CS + tid];
    for (int d = tid; d < D; d += 256) xrow[d] = __half2float(xch[(size_t)m * D + d]);
    __syncthreads();
    __half* apr = ap + (size_t)m * (NC * D);
    #pragma unroll
    for (int c = 0; c < NC; c++) {
        float w = w8[c];
        for (int d = tid; d < D; d += 256)
            apr[c * D + d] = __float2half_rn(w * xrow[d]);
    }
}

// ---------------- fused attention: O = softmax(QK^T/sqrt(dh)) V ----------------
// qp/kp: [b,h,s,DHP] fp16 (cols 65..79 zero); vt: [b,h,dh,s] with row 65 = ones,
// rows 66..79 zero. ob: [b,s,D] fp16, cols h*65+dh.
// grid (S/128, B*H), 256 threads, 8 warps x 16 q-rows.
constexpr int QSM = 128 * 88 * 2;    // 22528 B
constexpr int VSM = 80 * 136 * 2;    // 21760 B
constexpr int ATT_SMEM = QSM + 2 * QSM + 2 * VSM;   // Q + K0/K1 + V0/V1 = 111104

__global__ __launch_bounds__(256)
void fused_attn(const __half* __restrict__ qp, const __half* __restrict__ kp,
                const __half* __restrict__ vt, __half* __restrict__ ob,
                float scale) {
    extern __shared__ __align__(16) unsigned char asm_[];
    const uint32_t sb = smem_u32(asm_);
    const uint32_t kbase = sb + QSM;
    const uint32_t vbase = sb + 3 * QSM;

    const int bh = blockIdx.y;
    const int q0 = blockIdx.x * 128;
    const __half* qb = qp + (size_t)bh * S * DHP;
    const __half* kb = kp + (size_t)bh * S * DHP;
    const __half* vb = vt + (size_t)bh * DHP * S;

    const int tid = threadIdx.x;
    const int warp = tid >> 5;
    const int lane = tid & 31;
    const int gid  = lane >> 2;
    const int tig  = lane & 3;
    const int arow = (lane & 7) + (((lane >> 3) & 1) << 3);
    const int akof = ((lane >> 4) & 1) << 3;
    const int brow = (lane & 7) + (((lane >> 4) & 1) << 3);
    const int bkof = ((lane >> 3) & 1) << 3;
    const int qw = warp * 16;

    auto stageKV = [&](int it, int st) {
        const int k0 = it * 128;
        const uint32_t kst = kbase + st * QSM;
        const uint32_t vst = vbase + st * VSM;
        #pragma unroll
        for (int i = 0; i < 5; i++) {
            int idx = tid + (i << 8);           // 0..1279
            int kr = idx / 10, kc = idx - kr * 10;
            cp16(kst + (uint32_t)(kr * 176 + kc * 16),
                 kb + (size_t)(k0 + kr) * DHP + kc * 8, 16);
            int vr = idx >> 4, vc = idx & 15;
            cp16(vst + (uint32_t)(vr * 272 + vc * 16),
                 vb + (size_t)vr * S + k0 + vc * 8, 16);
        }
        asm volatile("cp.async.commit_group;");
    };

    // Q tile + first KV stage in one group
    #pragma unroll
    for (int i = 0; i < 5; i++) {
        int idx = tid + (i << 8);
        int qr = idx / 10, qc = idx - qr * 10;
        cp16(sb + (uint32_t)(qr * 176 + qc * 16),
             qb + (size_t)(q0 + qr) * DHP + qc * 8, 16);
    }
    stageKV(0, 0);

    float Oa[10][4];
    #pragma unroll
    for (int i = 0; i < 10; i++)
        #pragma unroll
        for (int r = 0; r < 4; r++) Oa[i][r] = 0.f;

    constexpr int nKT = S / 128;   // 16
    int st = 0;
    for (int it = 0; it < nKT; it++) {
        if (it + 1 < nKT) {
            stageKV(it + 1, st ^ 1);
            asm volatile("cp.async.wait_group 1;");
        } else {
            asm volatile("cp.async.wait_group 0;");
        }
        __syncthreads();

        const uint32_t kst = kbase + st * QSM;
        const uint32_t vst = vbase + st * VSM;

        // S = Q K^T  (16 x 128 per warp)
        float Sa[16][4];
        #pragma unroll
        for (int i = 0; i < 16; i++)
            #pragma unroll
            for (int r = 0; r < 4; r++) Sa[i][r] = 0.f;

        #pragma unroll
        for (int kk = 0; kk < 5; kk++) {
            uint32_t aq[4];
            ldm_x4(aq, sb + (uint32_t)(((qw + arow) * 88 + kk * 16 + akof) << 1));
            #pragma unroll
            for (int p = 0; p < 8; p++) {
                uint32_t bk_[4];
                ldm_x4(bk_, kst + (uint32_t)(((p * 16 + brow) * 88 + kk * 16 + bkof) << 1));
                mma_f16(Sa[2 * p],     aq, &bk_[0]);
                mma_f16(Sa[2 * p + 1], aq, &bk_[2]);
            }
        }

        // P = exp(scale*S), packed C->A fragments
        uint32_t pk[8][4];
        #pragma unroll
        for (int p = 0; p < 8; p++) {
            pk[p][0] = h2u(__floats2half2_rn(__expf(Sa[2*p][0] * scale),
                                             __expf(Sa[2*p][1] * scale)));
            pk[p][1] = h2u(__floats2half2_rn(__expf(Sa[2*p][2] * scale),
                                             __expf(Sa[2*p][3] * scale)));
            pk[p][2] = h2u(__floats2half2_rn(__expf(Sa[2*p+1][0] * scale),
                                             __expf(Sa[2*p+1][1] * scale)));
            pk[p][3] = h2u(__floats2half2_rn(__expf(Sa[2*p+1][2] * scale),
                                             __expf(Sa[2*p+1][3] * scale)));
        }

        // O += P V   (16 x 80 per warp; col 65 accumulates row sum)
        #pragma unroll
        for (int p = 0; p < 8; p++) {
            #pragma unroll
            for (int dp = 0; dp < 5; dp++) {
                uint32_t bv[4];
                ldm_x4(bv, vst + (uint32_t)(((dp * 16 + brow) * 136 + p * 16 + bkof) << 1));
                mma_f16(Oa[2 * dp],     pk[p], &bv[0]);
                mma_f16(Oa[2 * dp + 1], pk[p], &bv[2]);
            }
        }
        __syncthreads();
        st ^= 1;
    }

    // normalize by row sum (col 65 = block 8, c1/c3 on tig==0) and store
    float l0 = __shfl_sync(0xffffffffu, Oa[8][1], lane & ~3);
    float l1 = __shfl_sync(0xffffffffu, Oa[8][3], lane & ~3);
    float i0 = 1.0f / l0;
    float i1 = 1.0f / l1;

    const int bb = bh >> 4, hh = bh & 15;
    const int row0 = q0 + qw + gid;
    const size_t ob0 = ((size_t)(bb * S) + row0) * D + hh * DH;
    const size_t ob1 = ob0 + (size_t)8 * D;

    #pragma unroll
    for (int j = 0; j < 9; j++) {
        int c0 = 8 * j + 2 * tig;
        if (c0 < DH) {
            ob[ob0 + c0] = __float2half_rn(Oa[j][0] * i0);
            ob[ob1 + c0] = __float2half_rn(Oa[j][2] * i1);
        }
        if (c0 + 1 < DH) {
            ob[ob0 + c0 + 1] = __float2half_rn(Oa[j][1] * i0);
            ob[ob1 + c0 + 1] = __float2half_rn(Oa[j][3] * i1);
        }
    }
}

// ---------------- fp16 GEMM: BK=64, 2-stage cp.async, ldmatrix ----------------
// MODE: 0 +bias | 1 relu(+bias) | 2 +bias+extra | 5 plain | 6 +sum_c w*bk
// SCAT: 0 none | 1 -> [b,h,s,DHP] | 2 -> [b,h,dh,s]
constexpr int ROWW  = 72;
constexpr int STAGE_B = 128 * ROWW * 2;
constexpr int HG_SMEM = 4 * STAGE_B;

template <int MODE, int SCAT, bool SEGB, bool OUTF32, bool DUAL, bool SAFEH>
__global__ __launch_bounds__(256, 2)
void hgemm(const __half* __restrict__ A, int lda,
           const __half* __restrict__ W, int ldw,
           const float* __restrict__ bias,
           void* __restrict__ Cv, int ldc,
           float* __restrict__ aux,
           int N_, int K_, int Nsrc,
           const float* __restrict__ extra, int eld, float scale,
           long long aS2, long long wS2,
           long long cS1, long long cS2,
           int segLen, long long segStride) {
    extern __shared__ __align__(16) unsigned char hsm[];
    const uint32_t as_base = smem_u32(hsm);
    const uint32_t bs_base = as_base + 2 * STAGE_B;

    const int z  = blockIdx.z;
    const __half* Ab = A + (size_t)z * aS2;
    const __half* Wb = W + (size_t)z * wS2;
    const size_t coff = (size_t)(z >> 4) * cS1 + (size_t)(z & 15) * cS2;

    const int m0  = blockIdx.y * 128;
    const int n0  = blockIdx.x * 128;
    const int tid = threadIdx.x;
    const int warp = tid >> 5;
    const int lane = tid & 31;
    const int gid  = lane >> 2;
    const int tig  = lane & 3;
    const int wm = warp & 1;
    const int wn = warp >> 1;

    const int arow = (lane & 7) + (((lane >> 3) & 1) << 3);
    const int akof = ((lane >> 4) & 1) << 3;
    const int brow = (lane & 7) + (((lane >> 4) & 1) << 3);
    const int bkof = ((lane >> 3) & 1) << 3;

    float acc[4][4][4];
    #pragma unroll
    for (int i = 0; i < 4; i++)
        #pragma unroll
        for (int j = 0; j < 4; j++)
            #pragma unroll
            for (int r = 0; r < 4; r++) acc[i][j][r] = 0.f;

    auto stage = [&](int it, int st) {
        const int k0 = it * 64;
        #pragma unroll
        for (int i = 0; i < 4; i++) {
            int idx = tid + (i << 8);
            int m = idx >> 3, c = idx & 7;
            int gk = k0 + c * 8;
            cp16(as_base + (uint32_t)(st * STAGE_B) + (uint32_t)(m * (ROWW * 2) + (c << 4)),
                 Ab + (size_t)(m0 + m) * lda + gk, gk < K_ ? 16 : 0);
            const __half* src;
            if constexpr (SEGB) {
                int seg = gk / segLen;
                int kl  = gk - seg * segLen;
                src = Wb + (size_t)seg * segStride + (size_t)(n0 + m) * ldw + kl;
            } else {
                src = Wb + (size_t)(n0 + m) * ldw + gk;
            }
            cp16(bs_base + (uint32_t)(st * STAGE_B) + (uint32_t)(m * (ROWW * 2) + (c << 4)),
                 src, ((n0 + m) < Nsrc && gk < K_) ? 16 : 0);
        }
        asm volatile("cp.async.commit_group;");
    };

    const int nT = (K_ + 63) >> 6;
    stage(0, 0);

    int st = 0;
    for (int it = 0; it < nT; it++) {
        if (it + 1 < nT) {
            stage(it + 1, st ^ 1);
            asm volatile("cp.async.wait_group 1;");
        } else {
            asm volatile("cp.async.wait_group 0;");
        }
        __syncthreads();

        const uint32_t aO = as_base + (uint32_t)(st * STAGE_B);
        const uint32_t bO = bs_base + (uint32_t)(st * STAGE_B);

        #pragma unroll
        for (int kb = 0; kb < 4; kb++) {
            uint32_t af[4][4], bq[2][4];
            #pragma unroll
            for (int ms = 0; ms < 4; ms++)
                ldm_x4(af[ms], aO + (uint32_t)((((wm * 64 + ms * 16 + arow) * ROWW)
                                                + kb * 16 + akof) << 1));
            #pragma unroll
            for (int p = 0; p < 2; p++)
                ldm_x4(bq[p], bO + (uint32_t)((((wn * 32 + p * 16 + brow) * ROWW)
                                               + kb * 16 + bkof) << 1));
            #pragma unroll
            for (int ms = 0; ms < 4; ms++) {
                mma_f16(acc[ms][0], af[ms], &bq[0][0]);
                mma_f16(acc[ms][1], af[ms], &bq[0][2]);
                mma_f16(acc[ms][2], af[ms], &bq[1][0]);
                mma_f16(acc[ms][3], af[ms], &bq[1][2]);
            }
        }
        __syncthreads();
        st ^= 1;
    }

    __half* Ch = (__half*)Cv;
    float*  Cf = (float*)Cv;

    auto epival = [&](float v, int row, int col) -> float {
        if constexpr (MODE == 0) {
            v += bias[col];
        } else if constexpr (MODE == 1) {
            v = fmaxf(v + bias[col], 0.f);
        } else if constexpr (MODE == 2) {
            v += bias[col] + extra[(size_t)row * eld + col];
        } else if constexpr (MODE == 6) {
            const float* wrow = extra + (size_t)row * eld;
            float bsum = 0.f;
            #pragma unroll
            for (int c = 0; c < NC; c++)
                bsum += wrow[c] * bias[(size_t)c * D + col];
            v += bsum;
        }
        return v;
    };

    #pragma unroll
    for (int ms = 0; ms < 4; ms++) {
        #pragma unroll
        for (int ns = 0; ns < 4; ns++) {
            #pragma unroll
            for (int half_r = 0; half_r < 2; half_r++) {
                const int row = m0 + wm * 64 + ms * 16 + gid + half_r * 8;
                const int col0 = n0 + wn * 32 + ns * 8 + tig * 2;
                float v0 = acc[ms][ns][half_r * 2];
                float v1 = acc[ms][ns][half_r * 2 + 1];
                if constexpr (SCAT == 0) {
                    if (col0 + 1 < N_) {
                        v0 = epival(v0, row, col0);
                        v1 = epival(v1, row, col0 + 1);
                        if constexpr (DUAL) {
                            aux[(size_t)row * ldc + col0]     = v0;
                            aux[(size_t)row * ldc + col0 + 1] = v1;
                        }
                        if constexpr (OUTF32) {
                            float2 p = make_float2(v0, v1);
                            *(float2*)&Cf[coff + (size_t)row * ldc + col0] = p;
                        } else if constexpr (SAFEH) {
                            Ch[coff + (size_t)row * ldc + col0]     = __float2half_rn(v0);
                            Ch[coff + (size_t)row * ldc + col0 + 1] = __float2half_rn(v1);
                        } else {
                            __half2 p = __floats2half2_rn(v0, v1);
                            *(__half2*)&Ch[coff + (size_t)row * ldc + col0] = p;
                        }
                    } else if (col0 < N_) {
                        v0 = epival(v0, row, col0);
                        if constexpr (DUAL) aux[(size_t)row * ldc + col0] = v0;
                        if constexpr (OUTF32) Cf[coff + (size_t)row * ldc + col0] = v0;
                        else Ch[coff + (size_t)row * ldc + col0] = __float2half_rn(v0);
                    }
                } else {
                    #pragma unroll
                    for (int e = 0; e < 2; e++) {
                        int col = col0 + e;
                        if (col < N_) {
                            float v = epival(e ? v1 : v0, row, col);
                            int bb = row >> 11, s = row & (S - 1);
                            int h = col / DH;
                            int dh = col - h * DH;
                            if constexpr (SCAT == 1)
                                Ch[(((size_t)(bb * H + h)) * S + s) * DHP + dh] =
                                    __float2half_rn(v);
                            else
                                Ch[(((size_t)(bb * H + h)) * DHP + dh) * S + s] =
                                    __float2half_rn(v);
                        }
                    }
                }
            }
        }
    }
}

// ---------------- launcher ----------------
extern "C" void kernel_launch(void* const* d_in, const int* in_sizes, int n_in,
                              void* d_out, int out_size) {
    const float* x    = (const float*)d_in[0];
    const float* cond = (const float*)d_in[1];
    const float* Wq   = (const float*)d_in[2];
    const float* bq   = (const float*)d_in[3];
    const float* Wv   = (const float*)d_in[4];
    const float* bv   = (const float*)d_in[5];
    const float* Wk   = (const float*)d_in[6];
    const float* bk   = (const float*)d_in[7];
    const float* Wo   = (const float*)d_in[8];
    const float* bo   = (const float*)d_in[9];
    const float* g1   = (const float*)d_in[10];
    const float* bn1  = (const float*)d_in[11];
    const float* g2   = (const float*)d_in[12];
    const float* bn2  = (const float*)d_in[13];
    const float* Wf1  = (const float*)d_in[14];
    const float* bf1  = (const float*)d_in[15];
    const float* Wf2  = (const float*)d_in[16];
    const float* bf2  = (const float*)d_in[17];
    float* out = (float*)d_out;

    unsigned char* ar = nullptr;
    cudaGetSymbolAddress((void**)&ar, g_arena);
    __half* xch = (__half*)(ar + O_XCH);
    float*  xnf = (float*) (ar + O_XNF);
    __half* qp  = (__half*)(ar + O_QP);
    __half* kp  = (__half*)(ar + O_KP);
    __half* vt  = (__half*)(ar + O_VT);
    __half* ob  = (__half*)(ar + O_OB);
    __half* hbh = (__half*)(ar + O_HBH);
    float*  hbf = (float*) (ar + O_HBF);
    __half* ff  = (__half*)(ar + O_FF);
    float*  yb  = (float*) (ar + O_YB);
    __half* ap  = (__half*)(ar + O_AP);
    __half* wqh = (__half*)(ar + O_WQ);
    __half* wvh = (__half*)(ar + O_WV);
    __half* woh = (__half*)(ar + O_WO);
    __half* wkh = (__half*)(ar + O_WK);
    __half* wf1h = (__half*)(ar + O_WF1);
    __half* wf2h = (__half*)(ar + O_WF2);

    const float attn_scale = 1.0f / sqrtf((float)DH);

    cudaFuncSetAttribute(hgemm<0, 1, false, false, false, false>, cudaFuncAttributeMaxDynamicSharedMemorySize, HG_SMEM);
    cudaFuncSetAttribute(hgemm<0, 2, false, false, false, false>, cudaFuncAttributeMaxDynamicSharedMemorySize, HG_SMEM);
    cudaFuncSetAttribute(hgemm<6, 1, true,  false, false, false>, cudaFuncAttributeMaxDynamicSharedMemorySize, HG_SMEM);
    cudaFuncSetAttribute(hgemm<2, 0, false, false, true,  false>, cudaFuncAttributeMaxDynamicSharedMemorySize, HG_SMEM);
    cudaFuncSetAttribute(hgemm<1, 0, false, false, false, false>, cudaFuncAttributeMaxDynamicSharedMemorySize, HG_SMEM);
    cudaFuncSetAttribute(hgemm<2, 0, false, true,  false, false>, cudaFuncAttributeMaxDynamicSharedMemorySize, HG_SMEM);
    cudaFuncSetAttribute(fused_attn, cudaFuncAttributeMaxDynamicSharedMemorySize, ATT_SMEM);

    auto cvtw = [&](const float* src, __half* dst, size_t n) {
        int n8 = (int)(n / 8);
        w2h_kernel<<<(n8 + 255) / 256, 256>>>(src, dst, n8);
    };
    cvtw(Wq, wqh, (size_t)D * D);
    cvtw(Wv, wvh, (size_t)D * D);
    cvtw(Wo, woh, (size_t)D * D);
    cvtw(Wk, wkh, (size_t)NC * D * D);
    cvtw(Wf1, wf1h, (size_t)DFF * E);
    cvtw(Wf2, wf2h, (size_t)E * DFF);

    // ones row (dh==DH) of V^T for the row-sum column
    ones_row_kernel<<<B * H, 256>>>(vt);

    // 1. LN + concat
    ln_concat_kernel<<<MT, 256>>>(x, cond, g1, bn1, xch, xnf);

    // 2. A' = w * xc
    build_ap_kernel<<<MT, 256>>>(xch, cond, ap);

    const dim3 gD((D + 127) / 128, MT / 128);     // 9 x 64
    const dim3 gE(E / 128, MT / 128);             // 8 x 64
    const dim3 gF(DFF / 128, MT / 128);           // 32 x 64

    // 3. Q -> [b,h,s,DHP];  V -> transposed [b,h,dh,s] (rows 0..64)
    hgemm<0, 1, false, false, false, false><<<gD, 256, HG_SMEM>>>(
        xch, D, wqh, D, bq, qp, 0, nullptr, D, D, D,
        nullptr, 0, 0.f, 0, 0, 0, 0, 0, 0);
    hgemm<0, 2, false, false, false, false><<<gD, 256, HG_SMEM>>>(
        xch, D, wvh, D, bv, vt, 0, nullptr, D, D, D,
        nullptr, 0, 0.f, 0, 0, 0, 0, 0, 0);

    // 4. conditioned K: single GEMM K=8320 segmented over Wk[c]
    hgemm<6, 1, true, false, false, false><<<gD, 256, HG_SMEM>>>(
        ap, NC * D, wkh, D, bk, kp, 0, nullptr, D, NC * D, D,
        cond, CS, 0.f, 0, 0, 0, 0, D, (long long)D * D);

    // 5. fused attention (no score materialization)
    {
        dim3 g(S / 128, B * H);
        fused_attn<<<g, 256, ATT_SMEM>>>(qp, kp, vt, ob, attn_scale);
    }

    // 6. O-projection + residual xn -> hbh (half) + hbf (fp32)
    hgemm<2, 0, false, false, true, false><<<gE, 256, HG_SMEM>>>(
        ob, D, woh, D, bo, hbh, E, hbf, E, D, E,
        xnf, E, 0.f, 0, 0, 0, 0, 0, 0);

    // 7. FFN
    hgemm<1, 0, false, false, false, false><<<gF, 256, HG_SMEM>>>(
        hbh, E, wf1h, E, bf1, ff, DFF, nullptr, DFF, E, DFF,
        nullptr, 0, 0.f, 0, 0, 0, 0, 0, 0);
    hgemm<2, 0, false, true, false, false><<<gE, 256, HG_SMEM>>>(
        ff, DFF, wf2h, DFF, bf2, yb, E, nullptr, E, DFF, E,
        hbf, E, 0.f, 0, 0, 0, 0, 0, 0);

    // 8. final LN
    ln_final_kernel<<<MT, 256>>>(yb, g2, bn2, out);
}

// round 16
// speedup vs baseline: 1.5671x; 1.5671x over previous
#include <cuda_runtime.h>
#include <cuda_fp16.h>
#include <math.h>
#include <string.h>
#include <stdint.h>

// ---------------- problem constants ----------------
constexpr int B  = 4;
constexpr int S  = 2048;
constexpr int E  = 1024;
constexpr int CS = 16;
constexpr int NC = 8;
constexpr int H  = 16;
constexpr int D  = E + CS;      // 1040
constexpr int DH = D / H;       // 65
constexpr int DHP = 80;         // padded head dim
constexpr int DFF = 4 * E;      // 4096
constexpr int MT = B * S;       // 8192

// ---------------- arena (bytes) ----------------
constexpr size_t AL(size_t x) { return (x + 255) & ~(size_t)255; }
constexpr size_t SZ_XCH = (size_t)MT * D * 2;
constexpr size_t SZ_XNF = (size_t)MT * E * 4;
constexpr size_t SZ_HP  = (size_t)B * H * S * DHP * 2;
constexpr size_t SZ_OB  = (size_t)MT * D * 2;
constexpr size_t SZ_HBH = (size_t)MT * E * 2;
constexpr size_t SZ_HBF = (size_t)MT * E * 4;
constexpr size_t SZ_FF  = (size_t)MT * DFF * 2;
constexpr size_t SZ_YB  = (size_t)MT * E * 4;
constexpr size_t SZ_AP  = (size_t)MT * NC * D * 2;
constexpr size_t SZ_WDD = (size_t)D * D * 2;
constexpr size_t SZ_WK  = (size_t)NC * D * D * 2;
constexpr size_t SZ_WF  = (size_t)DFF * E * 2;

constexpr size_t O_XCH = 0;
constexpr size_t O_XNF = AL(O_XCH + SZ_XCH);
constexpr size_t O_QP  = AL(O_XNF + SZ_XNF);
constexpr size_t O_KP  = AL(O_QP  + SZ_HP);
constexpr size_t O_VT  = AL(O_KP  + SZ_HP);
constexpr size_t O_OB  = AL(O_VT  + SZ_HP);
constexpr size_t O_HBH = AL(O_OB  + SZ_OB);
constexpr size_t O_HBF = AL(O_HBH + SZ_HBH);
constexpr size_t O_FF  = AL(O_HBF + SZ_HBF);
constexpr size_t O_YB  = AL(O_FF  + SZ_FF);
constexpr size_t O_AP  = AL(O_YB  + SZ_YB);
constexpr size_t O_WQ  = AL(O_AP  + SZ_AP);
constexpr size_t O_WV  = AL(O_WQ  + SZ_WDD);
constexpr size_t O_WO  = AL(O_WV  + SZ_WDD);
constexpr size_t O_WK  = AL(O_WO  + SZ_WDD);
constexpr size_t O_WF1 = AL(O_WK  + SZ_WK);
constexpr size_t O_WF2 = AL(O_WF1 + SZ_WF);
constexpr size_t ARENA_BYTES = O_WF2 + SZ_WF;

__device__ __align__(256) unsigned char g_arena[ARENA_BYTES];

// ---------------- helpers ----------------
__device__ __forceinline__ uint32_t smem_u32(const void* p) {
    uint32_t a;
    asm("{ .reg .u64 t; cvta.to.shared.u64 t, %1; cvt.u32.u64 %0, t; }" : "=r"(a) : "l"(p));
    return a;
}

__device__ __forceinline__ uint32_t h2u(__half2 h) {
    uint32_t u;
    memcpy(&u, &h, 4);
    return u;
}

__device__ __forceinline__ void mma_f16(float* c, const uint32_t* a, const uint32_t* b) {
    asm volatile(
        "mma.sync.aligned.m16n8k16.row.col.f32.f16.f16.f32 "
        "{%0,%1,%2,%3}, {%4,%5,%6,%7}, {%8,%9}, {%0,%1,%2,%3};"
        : "+f"(c[0]), "+f"(c[1]), "+f"(c[2]), "+f"(c[3])
        : "r"(a[0]), "r"(a[1]), "r"(a[2]), "r"(a[3]), "r"(b[0]), "r"(b[1]));
}

__device__ __forceinline__ void ldm_x4(uint32_t* r, uint32_t addr) {
    asm volatile("ldmatrix.sync.aligned.m8n8.x4.shared.b16 {%0,%1,%2,%3}, [%4];"
                 : "=r"(r[0]), "=r"(r[1]), "=r"(r[2]), "=r"(r[3]) : "r"(addr));
}

__device__ __forceinline__ void cp16(uint32_t dst, const void* src, int sz) {
    asm volatile("cp.async.cg.shared.global [%0], [%1], 16, %2;"
                 :: "r"(dst), "l"(src), "r"(sz));
}

__device__ __forceinline__ float blk_sum256(float v, float* red8) {
    #pragma unroll
    for (int o = 16; o > 0; o >>= 1) v += __shfl_xor_sync(0xffffffffu, v, o);
    __syncthreads();
    if ((threadIdx.x & 31) == 0) red8[threadIdx.x >> 5] = v;
    __syncthreads();
    if (threadIdx.x == 0) {
        float t = 0.f;
        #pragma unroll
        for (int i = 0; i < 8; i++) t += red8[i];
        red8[0] = t;
    }
    __syncthreads();
    return red8[0];
}

// ---------------- fp32 -> fp16 weight convert ----------------
__global__ void w2h_kernel(const float* __restrict__ src, __half* __restrict__ dst, int n8) {
    int i = blockIdx.x * blockDim.x + threadIdx.x;
    if (i < n8) {
        float4 a = ((const float4*)src)[2 * i];
        float4 b = ((const float4*)src)[2 * i + 1];
        __half h[8];
        h[0] = __float2half_rn(a.x); h[1] = __float2half_rn(a.y);
        h[2] = __float2half_rn(a.z); h[3] = __float2half_rn(a.w);
        h[4] = __float2half_rn(b.x); h[5] = __float2half_rn(b.y);
        h[6] = __float2half_rn(b.z); h[7] = __float2half_rn(b.w);
        ((uint4*)dst)[i] = *(const uint4*)h;
    }
}

// ---------------- ones row for V^T (sum column trick) ----------------
__global__ void ones_row_kernel(__half* __restrict__ vt) {
    const size_t base = ((size_t)blockIdx.x * DHP + DH) * S;
    uint4 v;
    v.x = v.y = v.z = v.w = 0x3C003C00u;   // 1.0h x8
    ((uint4*)(vt + base))[threadIdx.x] = v;
}

// ---------------- LayerNorm + concat ----------------
__global__ void ln_concat_kernel(const float* __restrict__ x,
                                 const float* __restrict__ cond,
                                 const float* __restrict__ g,
                                 const float* __restrict__ bta,
                                 __half* __restrict__ xch,
                                 float* __restrict__ xnf) {
    __shared__ float red8[8];
    const int s   = blockIdx.x;
    const int tid = threadIdx.x;
    const float* xr = x + (size_t)s * E;
    float v0 = xr[tid], v1 = xr[tid + 256], v2 = xr[tid + 512], v3 = xr[tid + 768];
    float mean = blk_sum256(v0 + v1 + v2 + v3, red8) * (1.0f / E);
    float d0 = v0 - mean, d1 = v1 - mean, d2 = v2 - mean, d3 = v3 - mean;
    float var = blk_sum256(d0 * d0 + d1 * d1 + d2 * d2 + d3 * d3, red8) * (1.0f / E);
    float rstd = rsqrtf(var + 1e-5f);
    __half* xo = xch + (size_t)s * D;
    float*  xf = xnf + (size_t)s * E;
    float r0 = d0 * rstd * g[tid      ] + bta[tid      ];
    float r1 = d1 * rstd * g[tid + 256] + bta[tid + 256];
    float r2 = d2 * rstd * g[tid + 512] + bta[tid + 512];
    float r3 = d3 * rstd * g[tid + 768] + bta[tid + 768];
    xo[tid] = __float2half_rn(r0);  xf[tid] = r0;
    xo[tid + 256] = __float2half_rn(r1);  xf[tid + 256] = r1;
    xo[tid + 512] = __float2half_rn(r2);  xf[tid + 512] = r2;
    xo[tid + 768] = __float2half_rn(r3);  xf[tid + 768] = r3;
    if (tid < CS) xo[E + tid] = __float2half_rn(cond[(size_t)s * CS + tid]);
}

// ---------------- final LayerNorm ----------------
__global__ void ln_final_kernel(const float* __restrict__ y,
                                const float* __restrict__ g,
                                const float* __restrict__ bta,
                                float* __restrict__ out) {
    __shared__ float red8[8];
    const int s   = blockIdx.x;
    const int tid = threadIdx.x;
    const float* yr = y + (size_t)s * E;
    float v0 = yr[tid], v1 = yr[tid + 256], v2 = yr[tid + 512], v3 = yr[tid + 768];
    float mean = blk_sum256(v0 + v1 + v2 + v3, red8) * (1.0f / E);
    float d0 = v0 - mean, d1 = v1 - mean, d2 = v2 - mean, d3 = v3 - mean;
    float var = blk_sum256(d0 * d0 + d1 * d1 + d2 * d2 + d3 * d3, red8) * (1.0f / E);
    float rstd = rsqrtf(var + 1e-5f);
    float* o = out + (size_t)s * E;
    o[tid      ] = d0 * rstd * g[tid      ] + bta[tid      ];
    o[tid + 256] = d1 * rstd * g[tid + 256] + bta[tid + 256];
    o[tid + 512] = d2 * rstd * g[tid + 512] + bta[tid + 512];
    o[tid + 768] = d3 * rstd * g[tid + 768] + bta[tid + 768];
}

// ---------------- build A' = w[m,c] * xc[m,d] (half) ----------------
__global__ void build_ap_kernel(const __half* __restrict__ xch,
                                const float* __restrict__ cond,
                                __half* __restrict__ ap) {
    __shared__ float xrow[D];
    __shared__ float w8[NC];
    const int m   = blockIdx.x;
    const int tid = threadIdx.x;
    if (tid < NC) w8[tid] = cond[(size_t)m * CS + tid];
    for (int d = tid; d < D; d += 256) xrow[d] = __half2float(xch[(size_t)m * D + d]);
    __syncthreads();
    __half* apr = ap + (size_t)m * (NC * D);
    #pragma unroll
    for (int c = 0; c < NC; c++) {
        float w = w8[c];
        for (int d = tid; d < D; d += 256)
            apr[c * D + d] = __float2half_rn(w * xrow[d]);
    }
}

// ---------------- fused attention: O = softmax(QK^T/sqrt(dh)) V ----------------
// K-tile = 64 rows (occupancy fix: <=128 regs, 68KB smem -> 2 CTAs/SM).
// qp/kp: [b,h,s,DHP] fp16 (cols 65..79 zero); vt: [b,h,dh,s] with row 65 = ones,
// rows 66..79 zero. ob: [b,s,D] fp16, cols h*65+dh.
// grid (S/128, B*H), 256 threads, 8 warps x 16 q-rows.
constexpr int QSM  = 128 * 88 * 2;    // 22528 B
constexpr int KSM  = 64 * 88 * 2;     // 11264 B per stage
constexpr int VSM  = 80 * 72 * 2;     // 11520 B per stage
constexpr int ATT_SMEM = QSM + 2 * KSM + 2 * VSM;   // 68096 B

__global__ __launch_bounds__(256, 2)
void fused_attn(const __half* __restrict__ qp, const __half* __restrict__ kp,
                const __half* __restrict__ vt, __half* __restrict__ ob,
                float scale) {
    extern __shared__ __align__(16) unsigned char asm_[];
    const uint32_t sb = smem_u32(asm_);
    const uint32_t kbase = sb + QSM;
    const uint32_t vbase = kbase + 2 * KSM;

    const int bh = blockIdx.y;
    const int q0 = blockIdx.x * 128;
    const __half* qb = qp + (size_t)bh * S * DHP;
    const __half* kb = kp + (size_t)bh * S * DHP;
    const __half* vb = vt + (size_t)bh * DHP * S;

    const int tid = threadIdx.x;
    const int warp = tid >> 5;
    const int lane = tid & 31;
    const int gid  = lane >> 2;
    const int tig  = lane & 3;
    const int arow = (lane & 7) + (((lane >> 3) & 1) << 3);
    const int akof = ((lane >> 4) & 1) << 3;
    const int brow = (lane & 7) + (((lane >> 4) & 1) << 3);
    const int bkof = ((lane >> 3) & 1) << 3;
    const int qw = warp * 16;

    auto stageKV = [&](int it, int st) {
        const int k0 = it * 64;
        const uint32_t kst = kbase + st * KSM;
        const uint32_t vst = vbase + st * VSM;
        #pragma unroll
        for (int i = 0; i < 5; i++) {
            int idx = tid + (i << 8);           // 0..1279
            if (idx < 640) {                    // K: 64 rows x 10 chunks
                int kr = idx / 10, kc = idx - kr * 10;
                cp16(kst + (uint32_t)(kr * 176 + kc * 16),
                     kb + (size_t)(k0 + kr) * DHP + kc * 8, 16);
            } else {                            // V: 80 rows x 8 chunks
                int j = idx - 640;
                int vr = j >> 3, vc = j & 7;
                cp16(vst + (uint32_t)(vr * 144 + vc * 16),
                     vb + (size_t)vr * S + k0 + vc * 8, 16);
            }
        }
        asm volatile("cp.async.commit_group;");
    };

    // Q tile + first KV stage
    #pragma unroll
    for (int i = 0; i < 5; i++) {
        int idx = tid + (i << 8);
        int qr = idx / 10, qc = idx - qr * 10;
        cp16(sb + (uint32_t)(qr * 176 + qc * 16),
             qb + (size_t)(q0 + qr) * DHP + qc * 8, 16);
    }
    stageKV(0, 0);

    float Oa[10][4];
    #pragma unroll
    for (int i = 0; i < 10; i++)
        #pragma unroll
        for (int r = 0; r < 4; r++) Oa[i][r] = 0.f;

    constexpr int nKT = S / 64;   // 32
    int st = 0;
    for (int it = 0; it < nKT; it++) {
        if (it + 1 < nKT) {
            stageKV(it + 1, st ^ 1);
            asm volatile("cp.async.wait_group 1;");
        } else {
            asm volatile("cp.async.wait_group 0;");
        }
        __syncthreads();

        const uint32_t kst = kbase + st * KSM;
        const uint32_t vst = vbase + st * VSM;

        // S = Q K^T  (16 x 64 per warp)
        float Sa[8][4];
        #pragma unroll
        for (int i = 0; i < 8; i++)
            #pragma unroll
            for (int r = 0; r < 4; r++) Sa[i][r] = 0.f;

        #pragma unroll
        for (int kk = 0; kk < 5; kk++) {
            uint32_t aq[4];
            ldm_x4(aq, sb + (uint32_t)(((qw + arow) * 88 + kk * 16 + akof) << 1));
            #pragma unroll
            for (int p = 0; p < 4; p++) {
                uint32_t bk_[4];
                ldm_x4(bk_, kst + (uint32_t)(((p * 16 + brow) * 88 + kk * 16 + bkof) << 1));
                mma_f16(Sa[2 * p],     aq, &bk_[0]);
                mma_f16(Sa[2 * p + 1], aq, &bk_[2]);
            }
        }

        // P = exp(scale*S), packed C->A fragments
        uint32_t pk[4][4];
        #pragma unroll
        for (int p = 0; p < 4; p++) {
            pk[p][0] = h2u(__floats2half2_rn(__expf(Sa[2*p][0] * scale),
                                             __expf(Sa[2*p][1] * scale)));
            pk[p][1] = h2u(__floats2half2_rn(__expf(Sa[2*p][2] * scale),
                                             __expf(Sa[2*p][3] * scale)));
            pk[p][2] = h2u(__floats2half2_rn(__expf(Sa[2*p+1][0] * scale),
                                             __expf(Sa[2*p+1][1] * scale)));
            pk[p][3] = h2u(__floats2half2_rn(__expf(Sa[2*p+1][2] * scale),
                                             __expf(Sa[2*p+1][3] * scale)));
        }

        // O += P V   (16 x 80 per warp; col 65 accumulates row sum)
        #pragma unroll
        for (int p = 0; p < 4; p++) {
            #pragma unroll
            for (int dp = 0; dp < 5; dp++) {
                uint32_t bv[4];
                ldm_x4(bv, vst + (uint32_t)(((dp * 16 + brow) * 72 + p * 16 + bkof) << 1));
                mma_f16(Oa[2 * dp],     pk[p], &bv[0]);
                mma_f16(Oa[2 * dp + 1], pk[p], &bv[2]);
            }
        }
        __syncthreads();
        st ^= 1;
    }

    // normalize by row sum (col 65 = block 8, c1/c3 on tig==0) and store
    float l0 = __shfl_sync(0xffffffffu, Oa[8][1], lane & ~3);
    float l1 = __shfl_sync(0xffffffffu, Oa[8][3], lane & ~3);
    float i0 = 1.0f / l0;
    float i1 = 1.0f / l1;

    const int bb = bh >> 4, hh = bh & 15;
    const int row0 = q0 + qw + gid;
    const size_t ob0 = ((size_t)(bb * S) + row0) * D + hh * DH;
    const size_t ob1 = ob0 + (size_t)8 * D;

    #pragma unroll
    for (int j = 0; j < 9; j++) {
        int c0 = 8 * j + 2 * tig;
        if (c0 < DH) {
            ob[ob0 + c0] = __float2half_rn(Oa[j][0] * i0);
            ob[ob1 + c0] = __float2half_rn(Oa[j][2] * i1);
        }
        if (c0 + 1 < DH) {
            ob[ob0 + c0 + 1] = __float2half_rn(Oa[j][1] * i0);
            ob[ob1 + c0 + 1] = __float2half_rn(Oa[j][3] * i1);
        }
    }
}

// ---------------- fp16 GEMM: BK=64, 2-stage cp.async, ldmatrix ----------------
// MODE: 0 +bias | 1 relu(+bias) | 2 +bias+extra | 5 plain | 6 +sum_c w*bk
// SCAT: 0 none | 1 -> [b,h,s,DHP] | 2 -> [b,h,dh,s]
constexpr int ROWW  = 72;
constexpr int STAGE_B = 128 * ROWW * 2;
constexpr int HG_SMEM = 4 * STAGE_B;

template <int MODE, int SCAT, bool SEGB, bool OUTF32, bool DUAL, bool SAFEH>
__global__ __launch_bounds__(256, 2)
void hgemm(const __half* __restrict__ A, int lda,
           const __half* __restrict__ W, int ldw,
           const float* __restrict__ bias,
           void* __restrict__ Cv, int ldc,
           float* __restrict__ aux,
           int N_, int K_, int Nsrc,
           const float* __restrict__ extra, int eld, float scale,
           long long aS2, long long wS2,
           long long cS1, long long cS2,
           int segLen, long long segStride) {
    extern __shared__ __align__(16) unsigned char hsm[];
    const uint32_t as_base = smem_u32(hsm);
    const uint32_t bs_base = as_base + 2 * STAGE_B;

    const int z  = blockIdx.z;
    const __half* Ab = A + (size_t)z * aS2;
    const __half* Wb = W + (size_t)z * wS2;
    const size_t coff = (size_t)(z >> 4) * cS1 + (size_t)(z & 15) * cS2;

    const int m0  = blockIdx.y * 128;
    const int n0  = blockIdx.x * 128;
    const int tid = threadIdx.x;
    const int warp = tid >> 5;
    const int lane = tid & 31;
    const int gid  = lane >> 2;
    const int tig  = lane & 3;
    const int wm = warp & 1;
    const int wn = warp >> 1;

    const int arow = (lane & 7) + (((lane >> 3) & 1) << 3);
    const int akof = ((lane >> 4) & 1) << 3;
    const int brow = (lane & 7) + (((lane >> 4) & 1) << 3);
    const int bkof = ((lane >> 3) & 1) << 3;

    float acc[4][4][4];
    #pragma unroll
    for (int i = 0; i < 4; i++)
        #pragma unroll
        for (int j = 0; j < 4; j++)
            #pragma unroll
            for (int r = 0; r < 4; r++) acc[i][j][r] = 0.f;

    auto stage = [&](int it, int st) {
        const int k0 = it * 64;
        #pragma unroll
        for (int i = 0; i < 4; i++) {
            int idx = tid + (i << 8);
            int m = idx >> 3, c = idx & 7;
            int gk = k0 + c * 8;
            cp16(as_base + (uint32_t)(st * STAGE_B) + (uint32_t)(m * (ROWW * 2) + (c << 4)),
                 Ab + (size_t)(m0 + m) * lda + gk, gk < K_ ? 16 : 0);
            const __half* src;
            if constexpr (SEGB) {
                int seg = gk / segLen;
                int kl  = gk - seg * segLen;
                src = Wb + (size_t)seg * segStride + (size_t)(n0 + m) * ldw + kl;
            } else {
                src = Wb + (size_t)(n0 + m) * ldw + gk;
            }
            cp16(bs_base + (uint32_t)(st * STAGE_B) + (uint32_t)(m * (ROWW * 2) + (c << 4)),
                 src, ((n0 + m) < Nsrc && gk < K_) ? 16 : 0);
        }
        asm volatile("cp.async.commit_group;");
    };

    const int nT = (K_ + 63) >> 6;
    stage(0, 0);

    int st = 0;
    for (int it = 0; it < nT; it++) {
        if (it + 1 < nT) {
            stage(it + 1, st ^ 1);
            asm volatile("cp.async.wait_group 1;");
        } else {
            asm volatile("cp.async.wait_group 0;");
        }
        __syncthreads();

        const uint32_t aO = as_base + (uint32_t)(st * STAGE_B);
        const uint32_t bO = bs_base + (uint32_t)(st * STAGE_B);

        #pragma unroll
        for (int kb = 0; kb < 4; kb++) {
            uint32_t af[4][4], bq[2][4];
            #pragma unroll
            for (int ms = 0; ms < 4; ms++)
                ldm_x4(af[ms], aO + (uint32_t)((((wm * 64 + ms * 16 + arow) * ROWW)
                                                + kb * 16 + akof) << 1));
            #pragma unroll
            for (int p = 0; p < 2; p++)
                ldm_x4(bq[p], bO + (uint32_t)((((wn * 32 + p * 16 + brow) * ROWW)
                                               + kb * 16 + bkof) << 1));
            #pragma unroll
            for (int ms = 0; ms < 4; ms++) {
                mma_f16(acc[ms][0], af[ms], &bq[0][0]);
                mma_f16(acc[ms][1], af[ms], &bq[0][2]);
                mma_f16(acc[ms][2], af[ms], &bq[1][0]);
                mma_f16(acc[ms][3], af[ms], &bq[1][2]);
            }
        }
        __syncthreads();
        st ^= 1;
    }

    __half* Ch = (__half*)Cv;
    float*  Cf = (float*)Cv;

    auto epival = [&](float v, int row, int col) -> float {
        if constexpr (MODE == 0) {
            v += bias[col];
        } else if constexpr (MODE == 1) {
            v = fmaxf(v + bias[col], 0.f);
        } else if constexpr (MODE == 2) {
            v += bias[col] + extra[(size_t)row * eld + col];
        } else if constexpr (MODE == 6) {
            const float* wrow = extra + (size_t)row * eld;
            float bsum = 0.f;
            #pragma unroll
            for (int c = 0; c < NC; c++)
                bsum += wrow[c] * bias[(size_t)c * D + col];
            v += bsum;
        }
        return v;
    };

    #pragma unroll
    for (int ms = 0; ms < 4; ms++) {
        #pragma unroll
        for (int ns = 0; ns < 4; ns++) {
            #pragma unroll
            for (int half_r = 0; half_r < 2; half_r++) {
                const int row = m0 + wm * 64 + ms * 16 + gid + half_r * 8;
                const int col0 = n0 + wn * 32 + ns * 8 + tig * 2;
                float v0 = acc[ms][ns][half_r * 2];
                float v1 = acc[ms][ns][half_r * 2 + 1];
                if constexpr (SCAT == 0) {
                    if (col0 + 1 < N_) {
                        v0 = epival(v0, row, col0);
                        v1 = epival(v1, row, col0 + 1);
                        if constexpr (DUAL) {
                            aux[(size_t)row * ldc + col0]     = v0;
                            aux[(size_t)row * ldc + col0 + 1] = v1;
                        }
                        if constexpr (OUTF32) {
                            float2 p = make_float2(v0, v1);
                            *(float2*)&Cf[coff + (size_t)row * ldc + col0] = p;
                        } else if constexpr (SAFEH) {
                            Ch[coff + (size_t)row * ldc + col0]     = __float2half_rn(v0);
                            Ch[coff + (size_t)row * ldc + col0 + 1] = __float2half_rn(v1);
                        } else {
                            __half2 p = __floats2half2_rn(v0, v1);
                            *(__half2*)&Ch[coff + (size_t)row * ldc + col0] = p;
                        }
                    } else if (col0 < N_) {
                        v0 = epival(v0, row, col0);
                        if constexpr (DUAL) aux[(size_t)row * ldc + col0] = v0;
                        if constexpr (OUTF32) Cf[coff + (size_t)row * ldc + col0] = v0;
                        else Ch[coff + (size_t)row * ldc + col0] = __float2half_rn(v0);
                    }
                } else {
                    #pragma unroll
                    for (int e = 0; e < 2; e++) {
                        int col = col0 + e;
                        if (col < N_) {
                            float v = epival(e ? v1 : v0, row, col);
                            int bb = row >> 11, s = row & (S - 1);
                            int h = col / DH;
                            int dh = col - h * DH;
                            if constexpr (SCAT == 1)
                                Ch[(((size_t)(bb * H + h)) * S + s) * DHP + dh] =
                                    __float2half_rn(v);
                            else
                                Ch[(((size_t)(bb * H + h)) * DHP + dh) * S + s] =
                                    __float2half_rn(v);
                        }
                    }
                }
            }
        }
    }
}

// ---------------- launcher ----------------
extern "C" void kernel_launch(void* const* d_in, const int* in_sizes, int n_in,
                              void* d_out, int out_size) {
    const float* x    = (const float*)d_in[0];
    const float* cond = (const float*)d_in[1];
    const float* Wq   = (const float*)d_in[2];
    const float* bq   = (const float*)d_in[3];
    const float* Wv   = (const float*)d_in[4];
    const float* bv   = (const float*)d_in[5];
    const float* Wk   = (const float*)d_in[6];
    const float* bk   = (const float*)d_in[7];
    const float* Wo   = (const float*)d_in[8];
    const float* bo   = (const float*)d_in[9];
    const float* g1   = (const float*)d_in[10];
    const float* bn1  = (const float*)d_in[11];
    const float* g2   = (const float*)d_in[12];
    const float* bn2  = (const float*)d_in[13];
    const float* Wf1  = (const float*)d_in[14];
    const float* bf1  = (const float*)d_in[15];
    const float* Wf2  = (const float*)d_in[16];
    const float* bf2  = (const float*)d_in[17];
    float* out = (float*)d_out;

    unsigned char* ar = nullptr;
    cudaGetSymbolAddress((void**)&ar, g_arena);
    __half* xch = (__half*)(ar + O_XCH);
    float*  xnf = (float*) (ar + O_XNF);
    __half* qp  = (__half*)(ar + O_QP);
    __half* kp  = (__half*)(ar + O_KP);
    __half* vt  = (__half*)(ar + O_VT);
    __half* ob  = (__half*)(ar + O_OB);
    __half* hbh = (__half*)(ar + O_HBH);
    float*  hbf = (float*) (ar + O_HBF);
    __half* ff  = (__half*)(ar + O_FF);
    float*  yb  = (float*) (ar + O_YB);
    __half* ap  = (__half*)(ar + O_AP);
    __half* wqh = (__half*)(ar + O_WQ);
    __half* wvh = (__half*)(ar + O_WV);
    __half* woh = (__half*)(ar + O_WO);
    __half* wkh = (__half*)(ar + O_WK);
    __half* wf1h = (__half*)(ar + O_WF1);
    __half* wf2h = (__half*)(ar + O_WF2);

    const float attn_scale = 1.0f / sqrtf((float)DH);

    cudaFuncSetAttribute(hgemm<0, 1, false, false, false, false>, cudaFuncAttributeMaxDynamicSharedMemorySize, HG_SMEM);
    cudaFuncSetAttribute(hgemm<0, 2, false, false, false, false>, cudaFuncAttributeMaxDynamicSharedMemorySize, HG_SMEM);
    cudaFuncSetAttribute(hgemm<6, 1, true,  false, false, false>, cudaFuncAttributeMaxDynamicSharedMemorySize, HG_SMEM);
    cudaFuncSetAttribute(hgemm<2, 0, false, false, true,  false>, cudaFuncAttributeMaxDynamicSharedMemorySize, HG_SMEM);
    cudaFuncSetAttribute(hgemm<1, 0, false, false, false, false>, cudaFuncAttributeMaxDynamicSharedMemorySize, HG_SMEM);
    cudaFuncSetAttribute(hgemm<2, 0, false, true,  false, false>, cudaFuncAttributeMaxDynamicSharedMemorySize, HG_SMEM);
    cudaFuncSetAttribute(fused_attn, cudaFuncAttributeMaxDynamicSharedMemorySize, ATT_SMEM);

    auto cvtw = [&](const float* src, __half* dst, size_t n) {
        int n8 = (int)(n / 8);
        w2h_kernel<<<(n8 + 255) / 256, 256>>>(src, dst, n8);
    };
    cvtw(Wq, wqh, (size_t)D * D);
    cvtw(Wv, wvh, (size_t)D * D);
    cvtw(Wo, woh, (size_t)D * D);
    cvtw(Wk, wkh, (size_t)NC * D * D);
    cvtw(Wf1, wf1h, (size_t)DFF * E);
    cvtw(Wf2, wf2h, (size_t)E * DFF);

    // ones row (dh==DH) of V^T for the row-sum column
    ones_row_kernel<<<B * H, 256>>>(vt);

    // 1. LN + concat
    ln_concat_kernel<<<MT, 256>>>(x, cond, g1, bn1, xch, xnf);

    // 2. A' = w * xc
    build_ap_kernel<<<MT, 256>>>(xch, cond, ap);

    const dim3 gD((D + 127) / 128, MT / 128);     // 9 x 64
    const dim3 gE(E / 128, MT / 128);             // 8 x 64
    const dim3 gF(DFF / 128, MT / 128);           // 32 x 64

    // 3. Q -> [b,h,s,DHP];  V -> transposed [b,h,dh,s] (rows 0..64)
    hgemm<0, 1, false, false, false, false><<<gD, 256, HG_SMEM>>>(
        xch, D, wqh, D, bq, qp, 0, nullptr, D, D, D,
        nullptr, 0, 0.f, 0, 0, 0, 0, 0, 0);
    hgemm<0, 2, false, false, false, false><<<gD, 256, HG_SMEM>>>(
        xch, D, wvh, D, bv, vt, 0, nullptr, D, D, D,
        nullptr, 0, 0.f, 0, 0, 0, 0, 0, 0);

    // 4. conditioned K: single GEMM K=8320 segmented over Wk[c]
    hgemm<6, 1, true, false, false, false><<<gD, 256, HG_SMEM>>>(
        ap, NC * D, wkh, D, bk, kp, 0, nullptr, D, NC * D, D,
        cond, CS, 0.f, 0, 0, 0, 0, D, (long long)D * D);

    // 5. fused attention (no score materialization)
    {
        dim3 g(S / 128, B * H);
        fused_attn<<<g, 256, ATT_SMEM>>>(qp, kp, vt, ob, attn_scale);
    }

    // 6. O-projection + residual xn -> hbh (half) + hbf (fp32)
    hgemm<2, 0, false, false, true, false><<<gE, 256, HG_SMEM>>>(
        ob, D, woh, D, bo, hbh, E, hbf, E, D, E,
        xnf, E, 0.f, 0, 0, 0, 0, 0, 0);

    // 7. FFN
    hgemm<1, 0, false, false, false, false><<<gF, 256, HG_SMEM>>>(
        hbh, E, wf1h, E, bf1, ff, DFF, nullptr, DFF, E, DFF,
        nullptr, 0, 0.f, 0, 0, 0, 0, 0, 0);
    hgemm<2, 0, false, true, false, false><<<gE, 256, HG_SMEM>>>(
        ff, DFF, wf2h, DFF, bf2, yb, E, nullptr, E, DFF, E,
        hbf, E, 0.f, 0, 0, 0, 0, 0, 0);

    // 8. final LN
    ln_final_kernel<<<MT, 256>>>(yb, g2, bn2, out);
}

// round 17
// speedup vs baseline: 1.6043x; 1.0237x over previous
#include <cuda_runtime.h>
#include <cuda_fp16.h>
#include <math.h>
#include <string.h>
#include <stdint.h>

// ---------------- problem constants ----------------
constexpr int B  = 4;
constexpr int S  = 2048;
constexpr int E  = 1024;
constexpr int CS = 16;
constexpr int NC = 8;
constexpr int H  = 16;
constexpr int D  = E + CS;      // 1040
constexpr int DH = D / H;       // 65
constexpr int DHP = 80;         // padded head dim
constexpr int DFF = 4 * E;      // 4096
constexpr int MT = B * S;       // 8192

// ---------------- arena (bytes) ----------------
constexpr size_t AL(size_t x) { return (x + 255) & ~(size_t)255; }
constexpr size_t SZ_XCH = (size_t)MT * D * 2;
constexpr size_t SZ_XNF = (size_t)MT * E * 4;
constexpr size_t SZ_HP  = (size_t)B * H * S * DHP * 2;
constexpr size_t SZ_OB  = (size_t)MT * D * 2;
constexpr size_t SZ_HBH = (size_t)MT * E * 2;
constexpr size_t SZ_HBF = (size_t)MT * E * 4;
constexpr size_t SZ_FF  = (size_t)MT * DFF * 2;
constexpr size_t SZ_YB  = (size_t)MT * E * 4;
constexpr size_t SZ_AP  = (size_t)MT * NC * D * 2;
constexpr size_t SZ_WDD = (size_t)D * D * 2;
constexpr size_t SZ_WK  = (size_t)NC * D * D * 2;
constexpr size_t SZ_WF  = (size_t)DFF * E * 2;

constexpr size_t O_XCH = 0;
constexpr size_t O_XNF = AL(O_XCH + SZ_XCH);
constexpr size_t O_QP  = AL(O_XNF + SZ_XNF);
constexpr size_t O_KP  = AL(O_QP  + SZ_HP);
constexpr size_t O_VT  = AL(O_KP  + SZ_HP);
constexpr size_t O_OB  = AL(O_VT  + SZ_HP);
constexpr size_t O_HBH = AL(O_OB  + SZ_OB);
constexpr size_t O_HBF = AL(O_HBH + SZ_HBH);
constexpr size_t O_FF  = AL(O_HBF + SZ_HBF);
constexpr size_t O_YB  = AL(O_FF  + SZ_FF);
constexpr size_t O_AP  = AL(O_YB  + SZ_YB);
constexpr size_t O_WQ  = AL(O_AP  + SZ_AP);
constexpr size_t O_WV  = AL(O_WQ  + SZ_WDD);
constexpr size_t O_WO  = AL(O_WV  + SZ_WDD);
constexpr size_t O_WK  = AL(O_WO  + SZ_WDD);
constexpr size_t O_WF1 = AL(O_WK  + SZ_WK);
constexpr size_t O_WF2 = AL(O_WF1 + SZ_WF);
constexpr size_t ARENA_BYTES = O_WF2 + SZ_WF;

__device__ __align__(256) unsigned char g_arena[ARENA_BYTES];

// ---------------- helpers ----------------
__device__ __forceinline__ uint32_t smem_u32(const void* p) {
    uint32_t a;
    asm("{ .reg .u64 t; cvta.to.shared.u64 t, %1; cvt.u32.u64 %0, t; }" : "=r"(a) : "l"(p));
    return a;
}

__device__ __forceinline__ uint32_t h2u(__half2 h) {
    uint32_t u;
    memcpy(&u, &h, 4);
    return u;
}

__device__ __forceinline__ void mma_f16(float* c, const uint32_t* a, const uint32_t* b) {
    asm volatile(
        "mma.sync.aligned.m16n8k16.row.col.f32.f16.f16.f32 "
        "{%0,%1,%2,%3}, {%4,%5,%6,%7}, {%8,%9}, {%0,%1,%2,%3};"
        : "+f"(c[0]), "+f"(c[1]), "+f"(c[2]), "+f"(c[3])
        : "r"(a[0]), "r"(a[1]), "r"(a[2]), "r"(a[3]), "r"(b[0]), "r"(b[1]));
}

__device__ __forceinline__ void ldm_x4(uint32_t* r, uint32_t addr) {
    asm volatile("ldmatrix.sync.aligned.m8n8.x4.shared.b16 {%0,%1,%2,%3}, [%4];"
                 : "=r"(r[0]), "=r"(r[1]), "=r"(r[2]), "=r"(r[3]) : "r"(addr));
}

__device__ __forceinline__ void cp16(uint32_t dst, const void* src, int sz) {
    asm volatile("cp.async.cg.shared.global [%0], [%1], 16, %2;"
                 :: "r"(dst), "l"(src), "r"(sz));
}

__device__ __forceinline__ float blk_sum256(float v, float* red8) {
    #pragma unroll
    for (int o = 16; o > 0; o >>= 1) v += __shfl_xor_sync(0xffffffffu, v, o);
    __syncthreads();
    if ((threadIdx.x & 31) == 0) red8[threadIdx.x >> 5] = v;
    __syncthreads();
    if (threadIdx.x == 0) {
        float t = 0.f;
        #pragma unroll
        for (int i = 0; i < 8; i++) t += red8[i];
        red8[0] = t;
    }
    __syncthreads();
    return red8[0];
}

// ---------------- fused fp32 -> fp16 weight convert (all 6 weights, 1 launch) ----------------
struct WCvt {
    const float* src[6];
    __half*      dst[6];
    int          cum[7];   // prefix sums in uint4 (8-element) units
};

__global__ void w2h_all_kernel(WCvt p) {
    int i = blockIdx.x * blockDim.x + threadIdx.x;
    #pragma unroll
    for (int s = 0; s < 6; s++) {
        if (i >= p.cum[s] && i < p.cum[s + 1]) {
            int j = i - p.cum[s];
            float4 a = ((const float4*)p.src[s])[2 * j];
            float4 b = ((const float4*)p.src[s])[2 * j + 1];
            __half h[8];
            h[0] = __float2half_rn(a.x); h[1] = __float2half_rn(a.y);
            h[2] = __float2half_rn(a.z); h[3] = __float2half_rn(a.w);
            h[4] = __float2half_rn(b.x); h[5] = __float2half_rn(b.y);
            h[6] = __float2half_rn(b.z); h[7] = __float2half_rn(b.w);
            ((uint4*)p.dst[s])[j] = *(const uint4*)h;
        }
    }
}

// ---------------- ones row for V^T (sum column trick) ----------------
__global__ void ones_row_kernel(__half* __restrict__ vt) {
    const size_t base = ((size_t)blockIdx.x * DHP + DH) * S;
    uint4 v;
    v.x = v.y = v.z = v.w = 0x3C003C00u;   // 1.0h x8
    ((uint4*)(vt + base))[threadIdx.x] = v;
}

// ---------------- LayerNorm + concat ----------------
__global__ void ln_concat_kernel(const float* __restrict__ x,
                                 const float* __restrict__ cond,
                                 const float* __restrict__ g,
                                 const float* __restrict__ bta,
                                 __half* __restrict__ xch,
                                 float* __restrict__ xnf) {
    __shared__ float red8[8];
    const int s   = blockIdx.x;
    const int tid = threadIdx.x;
    const float* xr = x + (size_t)s * E;
    float v0 = xr[tid], v1 = xr[tid + 256], v2 = xr[tid + 512], v3 = xr[tid + 768];
    float mean = blk_sum256(v0 + v1 + v2 + v3, red8) * (1.0f / E);
    float d0 = v0 - mean, d1 = v1 - mean, d2 = v2 - mean, d3 = v3 - mean;
    float var = blk_sum256(d0 * d0 + d1 * d1 + d2 * d2 + d3 * d3, red8) * (1.0f / E);
    float rstd = rsqrtf(var + 1e-5f);
    __half* xo = xch + (size_t)s * D;
    float*  xf = xnf + (size_t)s * E;
    float r0 = d0 * rstd * g[tid      ] + bta[tid      ];
    float r1 = d1 * rstd * g[tid + 256] + bta[tid + 256];
    float r2 = d2 * rstd * g[tid + 512] + bta[tid + 512];
    float r3 = d3 * rstd * g[tid + 768] + bta[tid + 768];
    xo[tid] = __float2half_rn(r0);  xf[tid] = r0;
    xo[tid + 256] = __float2half_rn(r1);  xf[tid + 256] = r1;
    xo[tid + 512] = __float2half_rn(r2);  xf[tid + 512] = r2;
    xo[tid + 768] = __float2half_rn(r3);  xf[tid + 768] = r3;
    if (tid < CS) xo[E + tid] = __float2half_rn(cond[(size_t)s * CS + tid]);
}

// ---------------- final LayerNorm ----------------
__global__ void ln_final_kernel(const float* __restrict__ y,
                                const float* __restrict__ g,
                                const float* __restrict__ bta,
                                float* __restrict__ out) {
    __shared__ float red8[8];
    const int s   = blockIdx.x;
    const int tid = threadIdx.x;
    const float* yr = y + (size_t)s * E;
    float v0 = yr[tid], v1 = yr[tid + 256], v2 = yr[tid + 512], v3 = yr[tid + 768];
    float mean = blk_sum256(v0 + v1 + v2 + v3, red8) * (1.0f / E);
    float d0 = v0 - mean, d1 = v1 - mean, d2 = v2 - mean, d3 = v3 - mean;
    float var = blk_sum256(d0 * d0 + d1 * d1 + d2 * d2 + d3 * d3, red8) * (1.0f / E);
    float rstd = rsqrtf(var + 1e-5f);
    float* o = out + (size_t)s * E;
    o[tid      ] = d0 * rstd * g[tid      ] + bta[tid      ];
    o[tid + 256] = d1 * rstd * g[tid + 256] + bta[tid + 256];
    o[tid + 512] = d2 * rstd * g[tid + 512] + bta[tid + 512];
    o[tid + 768] = d3 * rstd * g[tid + 768] + bta[tid + 768];
}

// ---------------- build A' = w[m,c] * xc[m,d] (half) ----------------
__global__ void build_ap_kernel(const __half* __restrict__ xch,
                                const float* __restrict__ cond,
                                __half* __restrict__ ap) {
    __shared__ float xrow[D];
    __shared__ float w8[NC];
    const int m   = blockIdx.x;
    const int tid = threadIdx.x;
    if (tid < NC) w8[tid] = cond[(size_t)m * CS + tid];
    for (int d = tid; d < D; d += 256) xrow[d] = __half2float(xch[(size_t)m * D + d]);
    __syncthreads();
    __half* apr = ap + (size_t)m * (NC * D);
    #pragma unroll
    for (int c = 0; c < NC; c++) {
        float w = w8[c];
        for (int d = tid; d < D; d += 256)
            apr[c * D + d] = __float2half_rn(w * xrow[d]);
    }
}

// ---------------- fused attention: O = softmax(QK^T/sqrt(dh)) V ----------------
// K-tile = 64 rows; single barrier per iteration.
constexpr int QSM  = 128 * 88 * 2;    // 22528 B
constexpr int KSM  = 64 * 88 * 2;     // 11264 B per stage
constexpr int VSM  = 80 * 72 * 2;     // 11520 B per stage
constexpr int ATT_SMEM = QSM + 2 * KSM + 2 * VSM;   // 68096 B

__global__ __launch_bounds__(256, 2)
void fused_attn(const __half* __restrict__ qp, const __half* __restrict__ kp,
                const __half* __restrict__ vt, __half* __restrict__ ob,
                float scale) {
    extern __shared__ __align__(16) unsigned char asm_[];
    const uint32_t sb = smem_u32(asm_);
    const uint32_t kbase = sb + QSM;
    const uint32_t vbase = kbase + 2 * KSM;

    const int bh = blockIdx.y;
    const int q0 = blockIdx.x * 128;
    const __half* qb = qp + (size_t)bh * S * DHP;
    const __half* kb = kp + (size_t)bh * S * DHP;
    const __half* vb = vt + (size_t)bh * DHP * S;

    const int tid = threadIdx.x;
    const int warp = tid >> 5;
    const int lane = tid & 31;
    const int gid  = lane >> 2;
    const int tig  = lane & 3;
    const int arow = (lane & 7) + (((lane >> 3) & 1) << 3);
    const int akof = ((lane >> 4) & 1) << 3;
    const int brow = (lane & 7) + (((lane >> 4) & 1) << 3);
    const int bkof = ((lane >> 3) & 1) << 3;
    const int qw = warp * 16;

    auto stageKV = [&](int it, int st) {
        const int k0 = it * 64;
        const uint32_t kst = kbase + st * KSM;
        const uint32_t vst = vbase + st * VSM;
        #pragma unroll
        for (int i = 0; i < 5; i++) {
            int idx = tid + (i << 8);
            if (idx < 640) {
                int kr = idx / 10, kc = idx - kr * 10;
                cp16(kst + (uint32_t)(kr * 176 + kc * 16),
                     kb + (size_t)(k0 + kr) * DHP + kc * 8, 16);
            } else {
                int j = idx - 640;
                int vr = j >> 3, vc = j & 7;
                cp16(vst + (uint32_t)(vr * 144 + vc * 16),
                     vb + (size_t)vr * S + k0 + vc * 8, 16);
            }
        }
        asm volatile("cp.async.commit_group;");
    };

    // Q tile + first KV stage (one group)
    #pragma unroll
    for (int i = 0; i < 5; i++) {
        int idx = tid + (i << 8);
        int qr = idx / 10, qc = idx - qr * 10;
        cp16(sb + (uint32_t)(qr * 176 + qc * 16),
             qb + (size_t)(q0 + qr) * DHP + qc * 8, 16);
    }
    stageKV(0, 0);

    float Oa[10][4];
    #pragma unroll
    for (int i = 0; i < 10; i++)
        #pragma unroll
        for (int r = 0; r < 4; r++) Oa[i][r] = 0.f;

    constexpr int nKT = S / 64;   // 32
    int st = 0;
    for (int it = 0; it < nKT; it++) {
        asm volatile("cp.async.wait_group 0;");
        __syncthreads();
        if (it + 1 < nKT) stageKV(it + 1, st ^ 1);

        const uint32_t kst = kbase + st * KSM;
        const uint32_t vst = vbase + st * VSM;

        float Sa[8][4];
        #pragma unroll
        for (int i = 0; i < 8; i++)
            #pragma unroll
            for (int r = 0; r < 4; r++) Sa[i][r] = 0.f;

        #pragma unroll
        for (int kk = 0; kk < 5; kk++) {
            uint32_t aq[4];
            ldm_x4(aq, sb + (uint32_t)(((qw + arow) * 88 + kk * 16 + akof) << 1));
            #pragma unroll
            for (int p = 0; p < 4; p++) {
                uint32_t bk_[4];
                ldm_x4(bk_, kst + (uint32_t)(((p * 16 + brow) * 88 + kk * 16 + bkof) << 1));
                mma_f16(Sa[2 * p],     aq, &bk_[0]);
                mma_f16(Sa[2 * p + 1], aq, &bk_[2]);
            }
        }

        uint32_t pk[4][4];
        #pragma unroll
        for (int p = 0; p < 4; p++) {
            pk[p][0] = h2u(__floats2half2_rn(__expf(Sa[2*p][0] * scale),
                                             __expf(Sa[2*p][1] * scale)));
            pk[p][1] = h2u(__floats2half2_rn(__expf(Sa[2*p][2] * scale),
                                             __expf(Sa[2*p][3] * scale)));
            pk[p][2] = h2u(__floats2half2_rn(__expf(Sa[2*p+1][0] * scale),
                                             __expf(Sa[2*p+1][1] * scale)));
            pk[p][3] = h2u(__floats2half2_rn(__expf(Sa[2*p+1][2] * scale),
                                             __expf(Sa[2*p+1][3] * scale)));
        }

        #pragma unroll
        for (int p = 0; p < 4; p++) {
            #pragma unroll
            for (int dp = 0; dp < 5; dp++) {
                uint32_t bv[4];
                ldm_x4(bv, vst + (uint32_t)(((dp * 16 + brow) * 72 + p * 16 + bkof) << 1));
                mma_f16(Oa[2 * dp],     pk[p], &bv[0]);
                mma_f16(Oa[2 * dp + 1], pk[p], &bv[2]);
            }
        }
        st ^= 1;
    }

    // normalize by row sum (col 65) and store
    float l0 = __shfl_sync(0xffffffffu, Oa[8][1], lane & ~3);
    float l1 = __shfl_sync(0xffffffffu, Oa[8][3], lane & ~3);
    float i0 = 1.0f / l0;
    float i1 = 1.0f / l1;

    const int bb = bh >> 4, hh = bh & 15;
    const int row0 = q0 + qw + gid;
    const size_t ob0 = ((size_t)(bb * S) + row0) * D + hh * DH;
    const size_t ob1 = ob0 + (size_t)8 * D;

    #pragma unroll
    for (int j = 0; j < 9; j++) {
        int c0 = 8 * j + 2 * tig;
        if (c0 < DH) {
            ob[ob0 + c0] = __float2half_rn(Oa[j][0] * i0);
            ob[ob1 + c0] = __float2half_rn(Oa[j][2] * i1);
        }
        if (c0 + 1 < DH) {
            ob[ob0 + c0 + 1] = __float2half_rn(Oa[j][1] * i0);
            ob[ob1 + c0 + 1] = __float2half_rn(Oa[j][3] * i1);
        }
    }
}

// ---------------- fp16 GEMM: BK=64, 2-stage, single-barrier, frag double-buffer ----------------
// MODE: 0 +bias | 1 relu(+bias) | 2 +bias+extra | 5 plain | 6 +sum_c w*bk
// SCAT: 0 none | 1 -> [b,h,s,DHP] | 2 -> [b,h,dh,s]
constexpr int ROWW  = 72;
constexpr int STAGE_B = 128 * ROWW * 2;
constexpr int HG_SMEM = 4 * STAGE_B;

template <int MODE, int SCAT, bool SEGB, bool OUTF32, bool DUAL, bool SAFEH>
__global__ __launch_bounds__(256, 2)
void hgemm(const __half* __restrict__ A, int lda,
           const __half* __restrict__ W, int ldw,
           const float* __restrict__ bias,
           void* __restrict__ Cv, int ldc,
           float* __restrict__ aux,
           int N_, int K_, int Nsrc,
           const float* __restrict__ extra, int eld, float scale,
           long long aS2, long long wS2,
           long long cS1, long long cS2,
           int segLen, long long segStride) {
    extern __shared__ __align__(16) unsigned char hsm[];
    const uint32_t as_base = smem_u32(hsm);
    const uint32_t bs_base = as_base + 2 * STAGE_B;

    const int z  = blockIdx.z;
    const __half* Ab = A + (size_t)z * aS2;
    const __half* Wb = W + (size_t)z * wS2;
    const size_t coff = (size_t)(z >> 4) * cS1 + (size_t)(z & 15) * cS2;

    const int m0  = blockIdx.y * 128;
    const int n0  = blockIdx.x * 128;
    const int tid = threadIdx.x;
    const int warp = tid >> 5;
    const int lane = tid & 31;
    const int gid  = lane >> 2;
    const int tig  = lane & 3;
    const int wm = warp & 1;
    const int wn = warp >> 1;

    const int arow = (lane & 7) + (((lane >> 3) & 1) << 3);
    const int akof = ((lane >> 4) & 1) << 3;
    const int brow = (lane & 7) + (((lane >> 4) & 1) << 3);
    const int bkof = ((lane >> 3) & 1) << 3;

    float acc[4][4][4];
    #pragma unroll
    for (int i = 0; i < 4; i++)
        #pragma unroll
        for (int j = 0; j < 4; j++)
            #pragma unroll
            for (int r = 0; r < 4; r++) acc[i][j][r] = 0.f;

    auto stage = [&](int it, int st) {
        const int k0 = it * 64;
        #pragma unroll
        for (int i = 0; i < 4; i++) {
            int idx = tid + (i << 8);
            int m = idx >> 3, c = idx & 7;
            int gk = k0 + c * 8;
            cp16(as_base + (uint32_t)(st * STAGE_B) + (uint32_t)(m * (ROWW * 2) + (c << 4)),
                 Ab + (size_t)(m0 + m) * lda + gk, gk < K_ ? 16 : 0);
            const __half* src;
            if constexpr (SEGB) {
                int seg = gk / segLen;
                int kl  = gk - seg * segLen;
                src = Wb + (size_t)seg * segStride + (size_t)(n0 + m) * ldw + kl;
            } else {
                src = Wb + (size_t)(n0 + m) * ldw + gk;
            }
            cp16(bs_base + (uint32_t)(st * STAGE_B) + (uint32_t)(m * (ROWW * 2) + (c << 4)),
                 src, ((n0 + m) < Nsrc && gk < K_) ? 16 : 0);
        }
        asm volatile("cp.async.commit_group;");
    };

    const int nT = (K_ + 63) >> 6;
    stage(0, 0);

    int st = 0;
    for (int it = 0; it < nT; it++) {
        asm volatile("cp.async.wait_group 0;");
        __syncthreads();
        if (it + 1 < nT) stage(it + 1, st ^ 1);

        const uint32_t aO = as_base + (uint32_t)(st * STAGE_B);
        const uint32_t bO = bs_base + (uint32_t)(st * STAGE_B);

        uint32_t af[2][4][4], bq[2][2][4];
        auto loadf = [&](int kb, int buf) {
            #pragma unroll
            for (int ms = 0; ms < 4; ms++)
                ldm_x4(af[buf][ms], aO + (uint32_t)((((wm * 64 + ms * 16 + arow) * ROWW)
                                                    + kb * 16 + akof) << 1));
            #pragma unroll
            for (int p = 0; p < 2; p++)
                ldm_x4(bq[buf][p], bO + (uint32_t)((((wn * 32 + p * 16 + brow) * ROWW)
                                                   + kb * 16 + bkof) << 1));
        };

        loadf(0, 0);
        #pragma unroll
        for (int kb = 0; kb < 4; kb++) {
            const int cur = kb & 1;
            if (kb < 3) loadf(kb + 1, cur ^ 1);
            #pragma unroll
            for (int ms = 0; ms < 4; ms++) {
                mma_f16(acc[ms][0], af[cur][ms], &bq[cur][0][0]);
                mma_f16(acc[ms][1], af[cur][ms], &bq[cur][0][2]);
                mma_f16(acc[ms][2], af[cur][ms], &bq[cur][1][0]);
                mma_f16(acc[ms][3], af[cur][ms], &bq[cur][1][2]);
            }
        }
        st ^= 1;
    }

    __half* Ch = (__half*)Cv;
    float*  Cf = (float*)Cv;

    auto epival = [&](float v, int row, int col) -> float {
        if constexpr (MODE == 0) {
            v += bias[col];
        } else if constexpr (MODE == 1) {
            v = fmaxf(v + bias[col], 0.f);
        } else if constexpr (MODE == 2) {
            v += bias[col] + extra[(size_t)row * eld + col];
        } else if constexpr (MODE == 6) {
            const float* wrow = extra + (size_t)row * eld;
            float bsum = 0.f;
            #pragma unroll
            for (int c = 0; c < NC; c++)
                bsum += wrow[c] * bias[(size_t)c * D + col];
            v += bsum;
        }
        return v;
    };

    #pragma unroll
    for (int ms = 0; ms < 4; ms++) {
        #pragma unroll
        for (int ns = 0; ns < 4; ns++) {
            #pragma unroll
            for (int half_r = 0; half_r < 2; half_r++) {
                const int row = m0 + wm * 64 + ms * 16 + gid + half_r * 8;
                const int col0 = n0 + wn * 32 + ns * 8 + tig * 2;
                float v0 = acc[ms][ns][half_r * 2];
                float v1 = acc[ms][ns][half_r * 2 + 1];
                if constexpr (SCAT == 0) {
                    if (col0 + 1 < N_) {
                        v0 = epival(v0, row, col0);
                        v1 = epival(v1, row, col0 + 1);
                        if constexpr (DUAL) {
                            aux[(size_t)row * ldc + col0]     = v0;
                            aux[(size_t)row * ldc + col0 + 1] = v1;
                        }
                        if constexpr (OUTF32) {
                            float2 p = make_float2(v0, v1);
                            *(float2*)&Cf[coff + (size_t)row * ldc + col0] = p;
                        } else if constexpr (SAFEH) {
                            Ch[coff + (size_t)row * ldc + col0]     = __float2half_rn(v0);
                            Ch[coff + (size_t)row * ldc + col0 + 1] = __float2half_rn(v1);
                        } else {
                            __half2 p = __floats2half2_rn(v0, v1);
                            *(__half2*)&Ch[coff + (size_t)row * ldc + col0] = p;
                        }
                    } else if (col0 < N_) {
                        v0 = epival(v0, row, col0);
                        if constexpr (DUAL) aux[(size_t)row * ldc + col0] = v0;
                        if constexpr (OUTF32) Cf[coff + (size_t)row * ldc + col0] = v0;
                        else Ch[coff + (size_t)row * ldc + col0] = __float2half_rn(v0);
                    }
                } else {
                    #pragma unroll
                    for (int e = 0; e < 2; e++) {
                        int col = col0 + e;
                        if (col < N_) {
                            float v = epival(e ? v1 : v0, row, col);
                            int bb = row >> 11, s = row & (S - 1);
                            int h = col / DH;
                            int dh = col - h * DH;
                            if constexpr (SCAT == 1)
                                Ch[(((size_t)(bb * H + h)) * S + s) * DHP + dh] =
                                    __float2half_rn(v);
                            else
                                Ch[(((size_t)(bb * H + h)) * DHP + dh) * S + s] =
                                    __float2half_rn(v);
                        }
                    }
                }
            }
        }
    }
}

// ---------------- launcher ----------------
extern "C" void kernel_launch(void* const* d_in, const int* in_sizes, int n_in,
                              void* d_out, int out_size) {
    const float* x    = (const float*)d_in[0];
    const float* cond = (const float*)d_in[1];
    const float* Wq   = (const float*)d_in[2];
    const float* bq   = (const float*)d_in[3];
    const float* Wv   = (const float*)d_in[4];
    const float* bv   = (const float*)d_in[5];
    const float* Wk   = (const float*)d_in[6];
    const float* bk   = (const float*)d_in[7];
    const float* Wo   = (const float*)d_in[8];
    const float* bo   = (const float*)d_in[9];
    const float* g1   = (const float*)d_in[10];
    const float* bn1  = (const float*)d_in[11];
    const float* g2   = (const float*)d_in[12];
    const float* bn2  = (const float*)d_in[13];
    const float* Wf1  = (const float*)d_in[14];
    const float* bf1  = (const float*)d_in[15];
    const float* Wf2  = (const float*)d_in[16];
    const float* bf2  = (const float*)d_in[17];
    float* out = (float*)d_out;

    unsigned char* ar = nullptr;
    cudaGetSymbolAddress((void**)&ar, g_arena);
    __half* xch = (__half*)(ar + O_XCH);
    float*  xnf = (float*) (ar + O_XNF);
    __half* qp  = (__half*)(ar + O_QP);
    __half* kp  = (__half*)(ar + O_KP);
    __half* vt  = (__half*)(ar + O_VT);
    __half* ob  = (__half*)(ar + O_OB);
    __half* hbh = (__half*)(ar + O_HBH);
    float*  hbf = (float*) (ar + O_HBF);
    __half* ff  = (__half*)(ar + O_FF);
    float*  yb  = (float*) (ar + O_YB);
    __half* ap  = (__half*)(ar + O_AP);
    __half* wqh = (__half*)(ar + O_WQ);
    __half* wvh = (__half*)(ar + O_WV);
    __half* woh = (__half*)(ar + O_WO);
    __half* wkh = (__half*)(ar + O_WK);
    __half* wf1h = (__half*)(ar + O_WF1);
    __half* wf2h = (__half*)(ar + O_WF2);

    const float attn_scale = 1.0f / sqrtf((float)DH);

    cudaFuncSetAttribute(hgemm<0, 1, false, false, false, false>, cudaFuncAttributeMaxDynamicSharedMemorySize, HG_SMEM);
    cudaFuncSetAttribute(hgemm<0, 2, false, false, false, false>, cudaFuncAttributeMaxDynamicSharedMemorySize, HG_SMEM);
    cudaFuncSetAttribute(hgemm<6, 1, true,  false, false, false>, cudaFuncAttributeMaxDynamicSharedMemorySize, HG_SMEM);
    cudaFuncSetAttribute(hgemm<2, 0, false, false, true,  false>, cudaFuncAttributeMaxDynamicSharedMemorySize, HG_SMEM);
    cudaFuncSetAttribute(hgemm<1, 0, false, false, false, false>, cudaFuncAttributeMaxDynamicSharedMemorySize, HG_SMEM);
    cudaFuncSetAttribute(hgemm<2, 0, false, true,  false, false>, cudaFuncAttributeMaxDynamicSharedMemorySize, HG_SMEM);
    cudaFuncSetAttribute(fused_attn, cudaFuncAttributeMaxDynamicSharedMemorySize, ATT_SMEM);

    // single fused weight-convert launch
    {
        WCvt p;
        p.src[0] = Wq;  p.dst[0] = wqh;
        p.src[1] = Wv;  p.dst[1] = wvh;
        p.src[2] = Wo;  p.dst[2] = woh;
        p.src[3] = Wk;  p.dst[3] = wkh;
        p.src[4] = Wf1; p.dst[4] = wf1h;
        p.src[5] = Wf2; p.dst[5] = wf2h;
        const int n8s[6] = {
            (int)((size_t)D * D / 8), (int)((size_t)D * D / 8), (int)((size_t)D * D / 8),
            (int)((size_t)NC * D * D / 8),
            (int)((size_t)DFF * E / 8), (int)((size_t)E * DFF / 8)
        };
        p.cum[0] = 0;
        for (int i = 0; i < 6; i++) p.cum[i + 1] = p.cum[i] + n8s[i];
        w2h_all_kernel<<<(p.cum[6] + 255) / 256, 256>>>(p);
    }

    // ones row (dh==DH) of V^T for the row-sum column
    ones_row_kernel<<<B * H, 256>>>(vt);

    // 1. LN + concat
    ln_concat_kernel<<<MT, 256>>>(x, cond, g1, bn1, xch, xnf);

    // 2. A' = w * xc
    build_ap_kernel<<<MT, 256>>>(xch, cond, ap);

    const dim3 gD((D + 127) / 128, MT / 128);     // 9 x 64
    const dim3 gE(E / 128, MT / 128);             // 8 x 64
    const dim3 gF(DFF / 128, MT / 128);           // 32 x 64

    // 3. Q -> [b,h,s,DHP];  V -> transposed [b,h,dh,s] (rows 0..64)
    hgemm<0, 1, false, false, false, false><<<gD, 256, HG_SMEM>>>(
        xch, D, wqh, D, bq, qp, 0, nullptr, D, D, D,
        nullptr, 0, 0.f, 0, 0, 0, 0, 0, 0);
    hgemm<0, 2, false, false, false, false><<<gD, 256, HG_SMEM>>>(
        xch, D, wvh, D, bv, vt, 0, nullptr, D, D, D,
        nullptr, 0, 0.f, 0, 0, 0, 0, 0, 0);

    // 4. conditioned K: single GEMM K=8320 segmented over Wk[c]
    hgemm<6, 1, true, false, false, false><<<gD, 256, HG_SMEM>>>(
        ap, NC * D, wkh, D, bk, kp, 0, nullptr, D, NC * D, D,
        cond, CS, 0.f, 0, 0, 0, 0, D, (long long)D * D);

    // 5. fused attention (no score materialization)
    {
        dim3 g(S / 128, B * H);
        fused_attn<<<g, 256, ATT_SMEM>>>(qp, kp, vt, ob, attn_scale);
    }

    // 6. O-projection + residual xn -> hbh (half) + hbf (fp32)
    hgemm<2, 0, false, false, true, false><<<gE, 256, HG_SMEM>>>(
        ob, D, woh, D, bo, hbh, E, hbf, E, D, E,
        xnf, E, 0.f, 0, 0, 0, 0, 0, 0);

    // 7. FFN
    hgemm<1, 0, false, false, false, false><<<gF, 256, HG_SMEM>>>(
        hbh, E, wf1h, E, bf1, ff, DFF, nullptr, DFF, E, DFF,
        nullptr, 0, 0.f, 0, 0, 0, 0, 0, 0);
    hgemm<2, 0, false, true, false, false><<<gE, 256, HG_SMEM>>>(
        ff, DFF, wf2h, DFF, bf2, yb, E, nullptr, E, DFF, E,
        hbf, E, 0.f, 0, 0, 0, 0, 0, 0);

    // 8. final LN
    ln_final_kernel<<<MT, 256>>>(yb, g2, bn2, out);
}